// round 16
// baseline (speedup 1.0000x reference)
#include <cuda_runtime.h>
#include <cuda_fp16.h>
#include <cstdint>

#define B_   4
#define S_   2048
#define HID_ 1024
#define NHD_ 1024
#define EPS_ 1e-6f

// ---------------------------------------------------------------------------
// Packed-tile geometry: global operands stored as EXACT images of the smem
// stage, so one cp.async.bulk per tile replaces thousands of cp.async issues.
//   A tile: 2 k-sub x 128 rows x 80B (64B data + 16B pad)  = 20480 B
//   B tile: 64 rows x 272B (256B data + 16B pad)           = 17408 B
// ---------------------------------------------------------------------------
#define A_TILE_B 20480
#define B_TILE_B 17408
#define ATPK_BATCH ((size_t)16 * 32 * A_TILE_B)   // attn packed, per batch
#define VPK_BATCH  ((size_t)8  * 32 * B_TILE_B)   // value packed, per batch

__device__ __align__(16) unsigned char g_hs_pk[(size_t)64 * 16 * A_TILE_B]; // 21.0 MB
__device__ __align__(16) unsigned char g_wv_pk[(size_t)8  * 16 * B_TILE_B]; //  2.2 MB
__device__ __align__(16) unsigned char g_at_pk[(size_t)B_ * ATPK_BATCH];    // 41.9 MB
__device__ __align__(16) unsigned char g_v_pk [(size_t)B_ * VPK_BATCH];     // 17.8 MB

// ---------------------------------------------------------------------------
// Helpers (plain-sm_103-legal: cp.async.bulk / mbarrier / ldmatrix / mma.sync)
// ---------------------------------------------------------------------------
__device__ __forceinline__ uint32_t smem_u32(const void* p) {
    uint32_t a;
    asm("{ .reg .u64 t; cvta.to.shared.u64 t, %1; cvt.u32.u64 %0, t; }"
        : "=r"(a) : "l"(p));
    return a;
}
#define MBARRIER_INIT(addr, cnt) \
    asm volatile("mbarrier.init.shared.b64 [%0], %1;" :: "r"(addr), "r"(cnt) : "memory")
#define MBARRIER_EXPECT_TX(addr, bytes) \
    asm volatile("mbarrier.arrive.expect_tx.shared.b64 _, [%0], %1;" \
                 :: "r"(addr), "r"((uint32_t)(bytes)) : "memory")
#define MBARRIER_WAIT_PARITY(mbar_smem_addr, phase_parity) do { \
    uint32_t _mbar = (uint32_t)(mbar_smem_addr); \
    uint32_t _parity = (uint32_t)(phase_parity); \
    uint32_t _done; \
    asm volatile( \
        "{\n\t.reg .pred p;\n\t" \
        "mbarrier.try_wait.parity.acquire.cta.shared::cta.b64 p, [%1], %2;\n\t" \
        "selp.b32 %0, 1, 0, p;\n\t}" \
        : "=r"(_done) : "r"(_mbar), "r"(_parity) : "memory"); \
    if (!_done) { \
        asm volatile( \
            "{\n\t.reg .pred P1;\n\t" \
            "WAIT_LOOP_%=:\n\t" \
            "mbarrier.try_wait.parity.acquire.cta.shared::cta.b64 P1, [%0], %1, 0x989680;\n\t" \
            "@P1 bra.uni WAIT_DONE_%=;\n\t" \
            "bra.uni WAIT_LOOP_%=;\n\t" \
            "WAIT_DONE_%=:\n\t}" \
            :: "r"(_mbar), "r"(_parity) : "memory"); \
    } \
} while (0)

__device__ __forceinline__ void bulk_cp(uint32_t dst, const void* src,
                                        uint32_t bytes, uint32_t mbar) {
    asm volatile(
        "cp.async.bulk.shared::cluster.global.mbarrier::complete_tx::bytes "
        "[%0], [%1], %2, [%3];"
        :: "r"(dst), "l"(src), "r"(bytes), "r"(mbar) : "memory");
}

__device__ __forceinline__ void ldsm_x4(uint32_t* r, uint32_t a) {
    asm volatile("ldmatrix.sync.aligned.m8n8.x4.shared.b16 {%0,%1,%2,%3}, [%4];"
                 : "=r"(r[0]), "=r"(r[1]), "=r"(r[2]), "=r"(r[3]) : "r"(a));
}
__device__ __forceinline__ void ldsm_x4_t(uint32_t* r, uint32_t a) {
    asm volatile("ldmatrix.sync.aligned.m8n8.x4.trans.shared.b16 {%0,%1,%2,%3}, [%4];"
                 : "=r"(r[0]), "=r"(r[1]), "=r"(r[2]), "=r"(r[3]) : "r"(a));
}
__device__ __forceinline__ void mma_f16(float* c, const uint32_t* a, const uint32_t* b) {
    asm volatile(
        "mma.sync.aligned.m16n8k16.row.col.f32.f16.f16.f32 "
        "{%0,%1,%2,%3}, {%4,%5,%6,%7}, {%8,%9}, {%0,%1,%2,%3};"
        : "+f"(c[0]), "+f"(c[1]), "+f"(c[2]), "+f"(c[3])
        : "r"(a[0]), "r"(a[1]), "r"(a[2]), "r"(a[3]), "r"(b[0]), "r"(b[1]));
}

// ---------------------------------------------------------------------------
// Prep kernels — write PACKED tile layouts
// ---------------------------------------------------------------------------
__global__ __launch_bounds__(256) void attn_prep(const float* __restrict__ attn) {
    int row = blockIdx.x;              // b*S + q
    int b = row >> 11, q = row & (S_ - 1);
    const float* a = attn + (size_t)row * S_;
    float s = 0.f;
    for (int k = threadIdx.x; k <= q; k += 256) s += a[k];
    #pragma unroll
    for (int o = 16; o; o >>= 1) s += __shfl_down_sync(0xffffffffu, s, o);
    __shared__ float red[8];
    __shared__ float sinv;
    if ((threadIdx.x & 31) == 0) red[threadIdx.x >> 5] = s;
    __syncthreads();
    if (threadIdx.x == 0) {
        float t = 0.f;
        #pragma unroll
        for (int i = 0; i < 8; i++) t += red[i];
        sinv = 1.f / (EPS_ + t);
    }
    __syncthreads();
    float inv = sinv;
    unsigned char* base = g_at_pk + (size_t)b * ATPK_BATCH +
                          (size_t)(q >> 7) * 32 * A_TILE_B;
    const int row80 = (q & 127) * 80;
    const int climit = ((q >> 7) + 1) * 32;   // 4-col groups up to diag tile end
    for (int c = threadIdx.x; c < climit; c += 256) {
        int k = c * 4;
        float4 v = *reinterpret_cast<const float4*>(a + k);
        ushort4 o;
        o.x = __half_as_ushort(__float2half_rn((k + 0 <= q) ? v.x * inv : 0.f));
        o.y = __half_as_ushort(__float2half_rn((k + 1 <= q) ? v.y * inv : 0.f));
        o.z = __half_as_ushort(__float2half_rn((k + 2 <= q) ? v.z * inv : 0.f));
        o.w = __half_as_ushort(__float2half_rn((k + 3 <= q) ? v.w * inv : 0.f));
        unsigned char* p = base + (size_t)(k >> 6) * A_TILE_B +
                           ((k >> 5) & 1) * 10240 + row80 + (k & 31) * 2;
        *reinterpret_cast<ushort4*>(p) = o;
    }
}

__global__ __launch_bounds__(256) void pack_hs(const float* __restrict__ src) {
    size_t i = (size_t)blockIdx.x * 256 + threadIdx.x;   // float4 index
    float4 v = reinterpret_cast<const float4*>(src)[i];
    size_t e = i * 4;
    int s = (int)(e >> 10), k = (int)(e & 1023);
    ushort4 H;
    H.x = __half_as_ushort(__float2half_rn(v.x));
    H.y = __half_as_ushort(__float2half_rn(v.y));
    H.z = __half_as_ushort(__float2half_rn(v.z));
    H.w = __half_as_ushort(__float2half_rn(v.w));
    unsigned char* p = g_hs_pk +
        ((size_t)(s >> 7) * 16 + (k >> 6)) * A_TILE_B +
        ((k >> 5) & 1) * 10240 + (s & 127) * 80 + (k & 31) * 2;
    *reinterpret_cast<ushort4*>(p) = H;
}

__global__ __launch_bounds__(256) void pack_wv(const float* __restrict__ src) {
    size_t i = (size_t)blockIdx.x * 256 + threadIdx.x;   // float4 index
    float4 v = reinterpret_cast<const float4*>(src)[i];
    size_t e = i * 4;
    int kr = (int)(e >> 10), nc = (int)(e & 1023);
    ushort4 H;
    H.x = __half_as_ushort(__float2half_rn(v.x));
    H.y = __half_as_ushort(__float2half_rn(v.y));
    H.z = __half_as_ushort(__float2half_rn(v.z));
    H.w = __half_as_ushort(__float2half_rn(v.w));
    unsigned char* p = g_wv_pk +
        ((size_t)(nc >> 7) * 16 + (kr >> 6)) * B_TILE_B +
        (kr & 63) * 272 + (nc & 127) * 2;
    *reinterpret_cast<ushort4*>(p) = H;
}

// ---------------------------------------------------------------------------
// HMMA GEMM: C[m,n] = sum_k A[m,k]*B[k,n]  (fp16, fp32 acc)
// 128x128 CTA tile, BK=64, 8 warps (64x32), 3-stage bulk-copy pipeline,
// 2 CTAs/SM. Inner loop = proven R13 form (NO register double-buffering).
// CAUSAL: warps covering rows m0..m0+63 skip the final (diagonal) chunk —
// their masked A there is exactly zero.
// ---------------------------------------------------------------------------
static constexpr int OFF_A1 = 10240;
static constexpr int OFF_B  = 20480;
static constexpr int STG = 37888;            // == A_TILE_B + B_TILE_B
static constexpr int NSTG = 3;
static constexpr int GEMM_SMEM = NSTG * STG + 160;
// 113824 B/CTA * 2 CTAs = 227648 <= 228KB carveout (R15 confirmed occ=2 CTAs)

template <bool CAUSAL, bool PACK_EPI>
__global__ __launch_bounds__(256, 2) void mma_gemm(
    const unsigned char* __restrict__ Apk, const unsigned char* __restrict__ Bpk,
    float* __restrict__ Cf, unsigned char* __restrict__ Vpk,
    const float* __restrict__ bias,
    int nkTot, size_t strA_b, size_t strB_b, size_t strC) {
    extern __shared__ char dsm[];
    const uint32_t sb = (smem_u32(dsm) + 127) & ~127u;
    const uint32_t mbB = sb + NSTG * STG;     // mbarriers, 8B apart
    const int tid = threadIdx.x, lane = tid & 31, wid = tid >> 5;
    const int bx = blockIdx.x;
    const int by = CAUSAL ? (gridDim.y - 1 - blockIdx.y) : blockIdx.y;
    const int bz = blockIdx.z;
    const int m0 = by * 128, n0 = bx * 128;

    const unsigned char* Abase = Apk + (size_t)bz * strA_b +
                                 (size_t)by * nkTot * A_TILE_B;
    const unsigned char* Bbase = Bpk + (size_t)bz * strB_b +
                                 (size_t)bx * nkTot * B_TILE_B;

    const int nk = CAUSAL ? (by + 1) * 2 : nkTot;   // 64-k chunks (nk >= 2)

    if (tid < NSTG) MBARRIER_INIT(mbB + tid * 8, 1);
    __syncthreads();

    float acc[4][4][4];
    #pragma unroll
    for (int i = 0; i < 4; i++)
        #pragma unroll
        for (int j = 0; j < 4; j++)
            #pragma unroll
            for (int t = 0; t < 4; t++) acc[i][j][t] = 0.f;

    const int wm = (wid >> 2) * 64;
    const int wn = (wid & 3) * 32;

    auto fill = [&](int chunk) {
        const uint32_t mb = mbB + (chunk % NSTG) * 8;
        const uint32_t dst = sb + (chunk % NSTG) * STG;
        MBARRIER_EXPECT_TX(mb, STG);
        bulk_cp(dst,         Abase + (size_t)chunk * A_TILE_B, A_TILE_B, mb);
        bulk_cp(dst + OFF_B, Bbase + (size_t)chunk * B_TILE_B, B_TILE_B, mb);
    };

    // prologue: fill up to 3 stages
    if (tid == 0) {
        fill(0);
        fill(1);
        if (nk > 2) fill(2);
    }

    for (int kt = 0; kt < nk; kt++) {
        MBARRIER_WAIT_PARITY(mbB + (kt % NSTG) * 8, (kt / NSTG) & 1);
        const uint32_t st = sb + (kt % NSTG) * STG;

        // CAUSAL final chunk: k in [m0+64, m0+128). Rows m0..m0+63 (wm==0)
        // are fully masked there -> their warps skip ldsm+MMA (exact zeros).
        const bool active = !CAUSAL || (kt < nk - 1) || (wm == 64);
        if (active) {
            #pragma unroll
            for (int kk = 0; kk < 4; kk++) {
                const int sub = kk >> 1;
                const int k16 = (kk & 1) * 16;
                const int bk16 = kk * 16;
                uint32_t a_r[4][4], b_r[4][2];
                #pragma unroll
                for (int mt = 0; mt < 4; mt++) {
                    uint32_t off = sub * OFF_A1 +
                                   ((wm + mt * 16 + (lane & 15)) * 80 +
                                    (k16 + (lane >> 4) * 8) * 2);
                    ldsm_x4(a_r[mt], st + off);
                }
                #pragma unroll
                for (int np = 0; np < 2; np++) {
                    uint32_t off = ((bk16 + (lane & 15)) * 272 +
                                    (wn + np * 16 + (lane >> 4) * 8) * 2);
                    uint32_t t4[4];
                    ldsm_x4_t(t4, st + OFF_B + off);
                    b_r[np * 2][0] = t4[0]; b_r[np * 2][1] = t4[1];
                    b_r[np * 2 + 1][0] = t4[2]; b_r[np * 2 + 1][1] = t4[3];
                }
                #pragma unroll
                for (int mt = 0; mt < 4; mt++)
                    #pragma unroll
                    for (int nt = 0; nt < 4; nt++)
                        mma_f16(acc[mt][nt], a_r[mt], b_r[nt]);
            }
        }
        __syncthreads();            // stage consumed by all warps
        if (tid == 0 && kt + NSTG < nk) fill(kt + NSTG);
    }

    // epilogue
    const int gr = lane >> 2, gc = (lane & 3) * 2;
    #pragma unroll
    for (int mt = 0; mt < 4; mt++) {
        #pragma unroll
        for (int nt = 0; nt < 4; nt++) {
            const int col_in = wn + nt * 8 + gc;
            #pragma unroll
            for (int h = 0; h < 2; h++) {
                const int r = m0 + wm + mt * 16 + gr + h * 8;
                float v0 = acc[mt][nt][h * 2 + 0];
                float v1 = acc[mt][nt][h * 2 + 1];
                if (PACK_EPI) {
                    // write value in packed-B-tile format for GEMM2
                    const float2 bb =
                        *reinterpret_cast<const float2*>(bias + n0 + col_in);
                    v0 += bb.x; v1 += bb.y;
                    uint32_t hp =
                        (uint32_t)__half_as_ushort(__float2half_rn(v0)) |
                        ((uint32_t)__half_as_ushort(__float2half_rn(v1)) << 16);
                    const int b = r >> 11, r_b = r & 2047;
                    const int kc = r_b >> 6, ri = r_b & 63;
                    unsigned char* p = Vpk + (size_t)b * VPK_BATCH +
                                       (size_t)(bx * 32 + kc) * B_TILE_B +
                                       ri * 272 + col_in * 2;
                    *reinterpret_cast<uint32_t*>(p) = hp;
                } else {
                    float2 o; o.x = v0; o.y = v1;
                    *reinterpret_cast<float2*>(Cf + (size_t)bz * strC +
                                               (size_t)r * NHD_ + n0 + col_in) = o;
                }
            }
        }
    }
}

// ---------------------------------------------------------------------------
extern "C" void kernel_launch(void* const* d_in, const int* in_sizes, int n_in,
                              void* d_out, int out_size) {
    const float* hs    = (const float*)d_in[0];   // [B,S,HID]
    const float* assoc = (const float*)d_in[1];   // [B,S,S]
    // d_in[2] = broad_hc_attn (unused: broad_heads == 0)
    const float* Wv    = (const float*)d_in[3];   // [HID, NH*HD]
    const float* bv    = (const float*)d_in[4];   // [NH*HD]
    float*       out   = (float*)d_out;           // [B,S,NH*HD]
    (void)in_sizes; (void)n_in; (void)out_size;

    static cudaStream_t s2 = nullptr;
    static cudaEvent_t ev1 = nullptr, ev2 = nullptr;
    if (s2 == nullptr) {
        cudaStreamCreateWithFlags(&s2, cudaStreamNonBlocking);
        cudaEventCreateWithFlags(&ev1, cudaEventDisableTiming);
        cudaEventCreateWithFlags(&ev2, cudaEventDisableTiming);
    }

    cudaFuncSetAttribute(mma_gemm<false, true>,
                         cudaFuncAttributeMaxDynamicSharedMemorySize, GEMM_SMEM);
    cudaFuncSetAttribute(mma_gemm<true, false>,
                         cudaFuncAttributeMaxDynamicSharedMemorySize, GEMM_SMEM);

    unsigned char *hs_pk, *wv_pk, *at_pk, *v_pk;
    cudaGetSymbolAddress((void**)&hs_pk, g_hs_pk);
    cudaGetSymbolAddress((void**)&wv_pk, g_wv_pk);
    cudaGetSymbolAddress((void**)&at_pk, g_at_pk);
    cudaGetSymbolAddress((void**)&v_pk, g_v_pk);

    // fork: attn prep on side stream, overlapped with GEMM1's chain
    cudaEventRecord(ev1, 0);
    cudaStreamWaitEvent(s2, ev1, 0);
    attn_prep<<<B_ * S_, 256, 0, s2>>>(assoc);
    cudaEventRecord(ev2, s2);

    // main: pack hs + Wv, GEMM1 (value -> packed B-tiles)
    pack_hs<<<(int)(((size_t)B_ * S_ * HID_ / 4) / 256), 256>>>(hs);
    pack_wv<<<(int)(((size_t)HID_ * NHD_ / 4) / 256), 256>>>(Wv);
    mma_gemm<false, true><<<dim3(NHD_ / 128, (B_ * S_) / 128, 1), 256, GEMM_SMEM>>>(
        hs_pk, wv_pk, nullptr, v_pk, bv, 16, 0, 0, 0);

    // join, then GEMM2 (causal k-truncation, heavy blocks first)
    cudaStreamWaitEvent(0, ev2, 0);
    mma_gemm<true, false><<<dim3(NHD_ / 128, S_ / 128, B_), 256, GEMM_SMEM>>>(
        at_pk, v_pk, out, nullptr, nullptr,
        32, ATPK_BATCH, VPK_BATCH, (size_t)S_ * NHD_);
}

// round 17
// speedup vs baseline: 1.1166x; 1.1166x over previous
#include <cuda_runtime.h>
#include <cuda_fp16.h>
#include <cstdint>

#define B_   4
#define S_   2048
#define HID_ 1024
#define NHD_ 1024
#define EPS_ 1e-6f

// ---------------------------------------------------------------------------
// Packed-tile geometry (global operands = exact smem stage images)
//   A tile: 2 k-sub x 128 rows x 80B (64B data + 16B pad)  = 20480 B
//   B tile: 64 rows x 272B (256B data + 16B pad)           = 17408 B
// ---------------------------------------------------------------------------
#define A_TILE_B 20480
#define B_TILE_B 17408
#define ATPK_BATCH ((size_t)16 * 32 * A_TILE_B)   // attn packed, per batch
#define VPK_BATCH  ((size_t)8  * 32 * B_TILE_B)   // value packed, per batch

__device__ __align__(16) unsigned char g_hs_pk[(size_t)64 * 16 * A_TILE_B];
__device__ __align__(16) unsigned char g_wv_pk[(size_t)8  * 16 * B_TILE_B];
__device__ __align__(16) unsigned char g_at_pk[(size_t)B_ * ATPK_BATCH];
__device__ __align__(16) unsigned char g_v_pk [(size_t)B_ * VPK_BATCH];
__device__ int g_vflag[8 * 64];   // [bx][flat m-block] : V tiles ready

// ---------------------------------------------------------------------------
// Helpers (plain-sm_103-legal)
// ---------------------------------------------------------------------------
__device__ __forceinline__ uint32_t smem_u32(const void* p) {
    uint32_t a;
    asm("{ .reg .u64 t; cvta.to.shared.u64 t, %1; cvt.u32.u64 %0, t; }"
        : "=r"(a) : "l"(p));
    return a;
}
#define MBARRIER_INIT(addr, cnt) \
    asm volatile("mbarrier.init.shared.b64 [%0], %1;" :: "r"(addr), "r"(cnt) : "memory")
#define MBARRIER_EXPECT_TX(addr, bytes) \
    asm volatile("mbarrier.arrive.expect_tx.shared.b64 _, [%0], %1;" \
                 :: "r"(addr), "r"((uint32_t)(bytes)) : "memory")
#define MBARRIER_WAIT_PARITY(mbar_smem_addr, phase_parity) do { \
    uint32_t _mbar = (uint32_t)(mbar_smem_addr); \
    uint32_t _parity = (uint32_t)(phase_parity); \
    uint32_t _done; \
    asm volatile( \
        "{\n\t.reg .pred p;\n\t" \
        "mbarrier.try_wait.parity.acquire.cta.shared::cta.b64 p, [%1], %2;\n\t" \
        "selp.b32 %0, 1, 0, p;\n\t}" \
        : "=r"(_done) : "r"(_mbar), "r"(_parity) : "memory"); \
    if (!_done) { \
        asm volatile( \
            "{\n\t.reg .pred P1;\n\t" \
            "WAIT_LOOP_%=:\n\t" \
            "mbarrier.try_wait.parity.acquire.cta.shared::cta.b64 P1, [%0], %1, 0x989680;\n\t" \
            "@P1 bra.uni WAIT_DONE_%=;\n\t" \
            "bra.uni WAIT_LOOP_%=;\n\t" \
            "WAIT_DONE_%=:\n\t}" \
            :: "r"(_mbar), "r"(_parity) : "memory"); \
    } \
} while (0)

__device__ __forceinline__ void bulk_cp(uint32_t dst, const void* src,
                                        uint32_t bytes, uint32_t mbar) {
    asm volatile(
        "cp.async.bulk.shared::cluster.global.mbarrier::complete_tx::bytes "
        "[%0], [%1], %2, [%3];"
        :: "r"(dst), "l"(src), "r"(bytes), "r"(mbar) : "memory");
}

__device__ __forceinline__ void ldsm_x4(uint32_t* r, uint32_t a) {
    asm volatile("ldmatrix.sync.aligned.m8n8.x4.shared.b16 {%0,%1,%2,%3}, [%4];"
                 : "=r"(r[0]), "=r"(r[1]), "=r"(r[2]), "=r"(r[3]) : "r"(a));
}
__device__ __forceinline__ void ldsm_x4_t(uint32_t* r, uint32_t a) {
    asm volatile("ldmatrix.sync.aligned.m8n8.x4.trans.shared.b16 {%0,%1,%2,%3}, [%4];"
                 : "=r"(r[0]), "=r"(r[1]), "=r"(r[2]), "=r"(r[3]) : "r"(a));
}
__device__ __forceinline__ void mma_f16(float* c, const uint32_t* a, const uint32_t* b) {
    asm volatile(
        "mma.sync.aligned.m16n8k16.row.col.f32.f16.f16.f32 "
        "{%0,%1,%2,%3}, {%4,%5,%6,%7}, {%8,%9}, {%0,%1,%2,%3};"
        : "+f"(c[0]), "+f"(c[1]), "+f"(c[2]), "+f"(c[3])
        : "r"(a[0]), "r"(a[1]), "r"(a[2]), "r"(a[3]), "r"(b[0]), "r"(b[1]));
}

// ---------------------------------------------------------------------------
// Prep kernels — write PACKED tile layouts
// ---------------------------------------------------------------------------
__global__ void reset_flags() {
    if (threadIdx.x < 512) g_vflag[threadIdx.x] = 0;
}

__global__ __launch_bounds__(256) void attn_prep(const float* __restrict__ attn) {
    int row = blockIdx.x;              // b*S + q
    int b = row >> 11, q = row & (S_ - 1);
    const float* a = attn + (size_t)row * S_;
    float s = 0.f;
    for (int k = threadIdx.x; k <= q; k += 256) s += a[k];
    #pragma unroll
    for (int o = 16; o; o >>= 1) s += __shfl_down_sync(0xffffffffu, s, o);
    __shared__ float red[8];
    __shared__ float sinv;
    if ((threadIdx.x & 31) == 0) red[threadIdx.x >> 5] = s;
    __syncthreads();
    if (threadIdx.x == 0) {
        float t = 0.f;
        #pragma unroll
        for (int i = 0; i < 8; i++) t += red[i];
        sinv = 1.f / (EPS_ + t);
    }
    __syncthreads();
    float inv = sinv;
    unsigned char* base = g_at_pk + (size_t)b * ATPK_BATCH +
                          (size_t)(q >> 7) * 32 * A_TILE_B;
    const int row80 = (q & 127) * 80;
    const int climit = ((q >> 7) + 1) * 32;   // 4-col groups up to diag tile end
    for (int c = threadIdx.x; c < climit; c += 256) {
        int k = c * 4;
        float4 v = *reinterpret_cast<const float4*>(a + k);
        ushort4 o;
        o.x = __half_as_ushort(__float2half_rn((k + 0 <= q) ? v.x * inv : 0.f));
        o.y = __half_as_ushort(__float2half_rn((k + 1 <= q) ? v.y * inv : 0.f));
        o.z = __half_as_ushort(__float2half_rn((k + 2 <= q) ? v.z * inv : 0.f));
        o.w = __half_as_ushort(__float2half_rn((k + 3 <= q) ? v.w * inv : 0.f));
        unsigned char* p = base + (size_t)(k >> 6) * A_TILE_B +
                           ((k >> 5) & 1) * 10240 + row80 + (k & 31) * 2;
        *reinterpret_cast<ushort4*>(p) = o;
    }
}

__global__ __launch_bounds__(256) void pack_hs(const float* __restrict__ src) {
    size_t i = (size_t)blockIdx.x * 256 + threadIdx.x;   // float4 index
    float4 v = reinterpret_cast<const float4*>(src)[i];
    size_t e = i * 4;
    int s = (int)(e >> 10), k = (int)(e & 1023);
    ushort4 H;
    H.x = __half_as_ushort(__float2half_rn(v.x));
    H.y = __half_as_ushort(__float2half_rn(v.y));
    H.z = __half_as_ushort(__float2half_rn(v.z));
    H.w = __half_as_ushort(__float2half_rn(v.w));
    unsigned char* p = g_hs_pk +
        ((size_t)(s >> 7) * 16 + (k >> 6)) * A_TILE_B +
        ((k >> 5) & 1) * 10240 + (s & 127) * 80 + (k & 31) * 2;
    *reinterpret_cast<ushort4*>(p) = H;
}

__global__ __launch_bounds__(256) void pack_wv(const float* __restrict__ src) {
    size_t i = (size_t)blockIdx.x * 256 + threadIdx.x;   // float4 index
    float4 v = reinterpret_cast<const float4*>(src)[i];
    size_t e = i * 4;
    int kr = (int)(e >> 10), nc = (int)(e & 1023);
    ushort4 H;
    H.x = __half_as_ushort(__float2half_rn(v.x));
    H.y = __half_as_ushort(__float2half_rn(v.y));
    H.z = __half_as_ushort(__float2half_rn(v.z));
    H.w = __half_as_ushort(__float2half_rn(v.w));
    unsigned char* p = g_wv_pk +
        ((size_t)(nc >> 7) * 16 + (kr >> 6)) * B_TILE_B +
        (kr & 63) * 272 + (nc & 127) * 2;
    *reinterpret_cast<ushort4*>(p) = H;
}

// ---------------------------------------------------------------------------
// FUSED GEMM: bids 0..511 = G1 (value = hs@Wv + bv -> packed V + flag),
//             bids 512..1023 = G2 (out = attn@V, causal, flag-gated chunks).
// Pipeline = R13-proven: 128x128 CTA tile, BK=64, 2-stage bulk-copy,
// 2 CTAs/SM, fill-after-sync, single __syncthreads per chunk pair.
// ---------------------------------------------------------------------------
static constexpr int OFF_A1 = 10240;
static constexpr int OFF_B  = 20480;
static constexpr int STG = 37888;            // == A_TILE_B + B_TILE_B
static constexpr int GEMM_SMEM = 2 * STG + 160;

__global__ __launch_bounds__(256, 2) void fused_gemm(
    const unsigned char* __restrict__ hs_pk,
    const unsigned char* __restrict__ wv_pk,
    const unsigned char* __restrict__ at_pk,
    unsigned char* __restrict__ v_pk,
    float* __restrict__ out, const float* __restrict__ bias) {
    extern __shared__ char dsm[];
    const uint32_t sb = (smem_u32(dsm) + 127) & ~127u;
    const uint32_t mb0 = sb + 2 * STG, mb1 = sb + 2 * STG + 8;
    const int tid = threadIdx.x, lane = tid & 31, wid = tid >> 5;
    const int bid = blockIdx.x;
    const bool g2 = bid >= 512;

    int bx, by, bz, nk;
    const unsigned char *Abase, *Bbase;
    if (!g2) {
        bx = bid & 7; by = bid >> 3; bz = 0;
        nk = 16;
        Abase = hs_pk + (size_t)by * 16 * A_TILE_B;
        Bbase = wv_pk + (size_t)bx * 16 * B_TILE_B;
    } else {
        const int idx = bid - 512;
        bx = idx & 7;
        by = 15 - ((idx >> 3) & 15);       // heavy blocks first within batch
        bz = idx >> 7;
        nk = (by + 1) * 2;
        Abase = at_pk + (size_t)bz * ATPK_BATCH + (size_t)by * 32 * A_TILE_B;
        Bbase = v_pk + (size_t)bz * VPK_BATCH + (size_t)bx * 32 * B_TILE_B;
    }
    const int m0 = by * 128, n0 = bx * 128;

    if (tid < 2) MBARRIER_INIT(mb0 + tid * 8, 1);
    __syncthreads();

    float acc[4][4][4];
    #pragma unroll
    for (int i = 0; i < 4; i++)
        #pragma unroll
        for (int j = 0; j < 4; j++)
            #pragma unroll
            for (int t = 0; t < 4; t++) acc[i][j][t] = 0.f;

    const int wm = (wid >> 2) * 64;
    const int wn = (wid & 3) * 32;

    auto fill = [&](int chunk) {          // called by tid==0 only
        if (g2) {                         // gate on producer G1 CTA's flag
            volatile int* f = &g_vflag[bx * 64 + bz * 16 + (chunk >> 1)];
            while (*f == 0) __nanosleep(128);
        }
        const uint32_t mb = (chunk & 1) ? mb1 : mb0;
        const uint32_t dst = sb + (chunk & 1) * STG;
        MBARRIER_EXPECT_TX(mb, STG);
        bulk_cp(dst,         Abase + (size_t)chunk * A_TILE_B, A_TILE_B, mb);
        bulk_cp(dst + OFF_B, Bbase + (size_t)chunk * B_TILE_B, B_TILE_B, mb);
    };

    // prologue: both stages (nk >= 2 always)
    if (tid == 0) { fill(0); fill(1); }

    for (int kt = 0; kt < nk; kt++) {
        MBARRIER_WAIT_PARITY((kt & 1) ? mb1 : mb0, (kt >> 1) & 1);
        const uint32_t st = sb + (kt & 1) * STG;

        // causal diag chunk: rows m0..m0+63 (wm==0) fully masked -> skip
        const bool active = !g2 || (kt < nk - 1) || (wm == 64);
        if (active) {
            #pragma unroll
            for (int kk = 0; kk < 4; kk++) {
                const int sub = kk >> 1;
                const int k16 = (kk & 1) * 16;
                const int bk16 = kk * 16;
                uint32_t a_r[4][4], b_r[4][2];
                #pragma unroll
                for (int mt = 0; mt < 4; mt++) {
                    uint32_t off = sub * OFF_A1 +
                                   ((wm + mt * 16 + (lane & 15)) * 80 +
                                    (k16 + (lane >> 4) * 8) * 2);
                    ldsm_x4(a_r[mt], st + off);
                }
                #pragma unroll
                for (int np = 0; np < 2; np++) {
                    uint32_t off = ((bk16 + (lane & 15)) * 272 +
                                    (wn + np * 16 + (lane >> 4) * 8) * 2);
                    uint32_t t4[4];
                    ldsm_x4_t(t4, st + OFF_B + off);
                    b_r[np * 2][0] = t4[0]; b_r[np * 2][1] = t4[1];
                    b_r[np * 2 + 1][0] = t4[2]; b_r[np * 2 + 1][1] = t4[3];
                }
                #pragma unroll
                for (int mt = 0; mt < 4; mt++)
                    #pragma unroll
                    for (int nt = 0; nt < 4; nt++)
                        mma_f16(acc[mt][nt], a_r[mt], b_r[nt]);
            }
        }
        __syncthreads();            // stage consumed by all warps
        if (tid == 0 && kt + 2 < nk) fill(kt + 2);
    }

    // epilogue
    const int gr = lane >> 2, gc = (lane & 3) * 2;
    if (!g2) {
        #pragma unroll
        for (int mt = 0; mt < 4; mt++) {
            #pragma unroll
            for (int nt = 0; nt < 4; nt++) {
                const int col_in = wn + nt * 8 + gc;
                #pragma unroll
                for (int h = 0; h < 2; h++) {
                    const int r = m0 + wm + mt * 16 + gr + h * 8;
                    const float2 bb =
                        *reinterpret_cast<const float2*>(bias + n0 + col_in);
                    float v0 = acc[mt][nt][h * 2 + 0] + bb.x;
                    float v1 = acc[mt][nt][h * 2 + 1] + bb.y;
                    uint32_t hp =
                        (uint32_t)__half_as_ushort(__float2half_rn(v0)) |
                        ((uint32_t)__half_as_ushort(__float2half_rn(v1)) << 16);
                    const int b = r >> 11, r_b = r & 2047;
                    const int kc = r_b >> 6, ri = r_b & 63;
                    unsigned char* p = v_pk + (size_t)b * VPK_BATCH +
                                       (size_t)(bx * 32 + kc) * B_TILE_B +
                                       ri * 272 + col_in * 2;
                    *reinterpret_cast<uint32_t*>(p) = hp;
                }
            }
        }
        __threadfence();            // V tile visible before flag
        __syncthreads();
        if (tid == 0) atomicExch(&g_vflag[bx * 64 + by], 1);
    } else {
        float* Cb = out + (size_t)bz * S_ * NHD_;
        #pragma unroll
        for (int mt = 0; mt < 4; mt++) {
            #pragma unroll
            for (int nt = 0; nt < 4; nt++) {
                const int col = n0 + wn + nt * 8 + gc;
                #pragma unroll
                for (int h = 0; h < 2; h++) {
                    const int r = m0 + wm + mt * 16 + gr + h * 8;
                    float2 o;
                    o.x = acc[mt][nt][h * 2 + 0];
                    o.y = acc[mt][nt][h * 2 + 1];
                    *reinterpret_cast<float2*>(Cb + (size_t)r * NHD_ + col) = o;
                }
            }
        }
    }
}

// ---------------------------------------------------------------------------
extern "C" void kernel_launch(void* const* d_in, const int* in_sizes, int n_in,
                              void* d_out, int out_size) {
    const float* hs    = (const float*)d_in[0];   // [B,S,HID]
    const float* assoc = (const float*)d_in[1];   // [B,S,S]
    // d_in[2] = broad_hc_attn (unused: broad_heads == 0)
    const float* Wv    = (const float*)d_in[3];   // [HID, NH*HD]
    const float* bv    = (const float*)d_in[4];   // [NH*HD]
    float*       out   = (float*)d_out;           // [B,S,NH*HD]
    (void)in_sizes; (void)n_in; (void)out_size;

    static cudaStream_t s2 = nullptr;
    static cudaEvent_t ev1 = nullptr, ev2 = nullptr;
    if (s2 == nullptr) {
        cudaStreamCreateWithFlags(&s2, cudaStreamNonBlocking);
        cudaEventCreateWithFlags(&ev1, cudaEventDisableTiming);
        cudaEventCreateWithFlags(&ev2, cudaEventDisableTiming);
    }

    cudaFuncSetAttribute(fused_gemm,
                         cudaFuncAttributeMaxDynamicSharedMemorySize, GEMM_SMEM);

    unsigned char *hs_pk, *wv_pk, *at_pk, *v_pk;
    cudaGetSymbolAddress((void**)&hs_pk, g_hs_pk);
    cudaGetSymbolAddress((void**)&wv_pk, g_wv_pk);
    cudaGetSymbolAddress((void**)&at_pk, g_at_pk);
    cudaGetSymbolAddress((void**)&v_pk, g_v_pk);

    // flags must be clean before any G1 CTA can set them
    reset_flags<<<1, 512>>>();

    // fork: attn prep on side stream, overlapped with the pack kernels
    cudaEventRecord(ev1, 0);
    cudaStreamWaitEvent(s2, ev1, 0);
    attn_prep<<<B_ * S_, 256, 0, s2>>>(assoc);
    cudaEventRecord(ev2, s2);

    // main: pack hs + Wv
    pack_hs<<<(int)(((size_t)B_ * S_ * HID_ / 4) / 256), 256>>>(hs);
    pack_wv<<<(int)(((size_t)HID_ * NHD_ / 4) / 256), 256>>>(Wv);

    // join attn, then ONE fused launch: G1 (bids 0..511) + G2 (512..1023),
    // G2 chunk loads gated on G1 per-tile flags -> tail waves overlap.
    cudaStreamWaitEvent(0, ev2, 0);
    fused_gemm<<<1024, 256, GEMM_SMEM>>>(hs_pk, wv_pk, at_pk, v_pk, out, bv);
}